// round 3
// baseline (speedup 1.0000x reference)
#include <cuda_runtime.h>
#include <cuda_fp16.h>

#define NB 8
#define NN 1024
#define NF 128
#define NH 8

// -------- scratch (device globals; allocation is forbidden) --------
__device__ __half    g_Q[NB*NN*NF];      // [b*N+q][128], pre-scaled by log2e/4
__device__ __half    g_K[NB*NN*NF];      // [b*N+q][128]
__device__ __half    g_V[NB*NF*NN];      // [b][o=h*16+d][q]  (d-major for PV mma)
__device__ float     g_attn[NB*NN*NF];   // attention output before Wo
__device__ unsigned  g_mask[NB*NN*32];   // [b*N+q][word]; bit j of word w = A[..][w*32+j]>0

#define QSCALE 0.3606737602222409f   // log2(e)/4

// -------- helpers --------
static __device__ __forceinline__ float ex2f(float x){ float r; asm("ex2.approx.ftz.f32 %0,%1;":"=f"(r):"f"(x)); return r; }
static __device__ __forceinline__ float rcpf(float x){ float r; asm("rcp.approx.ftz.f32 %0,%1;":"=f"(r):"f"(x)); return r; }
static __device__ __forceinline__ unsigned long long pk2(float a,float b){
    unsigned long long r; asm("mov.b64 %0,{%1,%2};":"=l"(r):"f"(a),"f"(b)); return r; }
static __device__ __forceinline__ void upk2(unsigned long long p,float&a,float&b){
    asm("mov.b64 {%0,%1},%2;":"=f"(a),"=f"(b):"l"(p)); }
static __device__ __forceinline__ unsigned long long fma2(unsigned long long a,unsigned long long b,unsigned long long c){
    unsigned long long d; asm("fma.rn.f32x2 %0,%1,%2,%3;":"=l"(d):"l"(a),"l"(b),"l"(c)); return d; }
static __device__ __forceinline__ unsigned h2(float a,float b){
    __half2 h = __floats2half2_rn(a,b); return *reinterpret_cast<unsigned*>(&h); }
static __device__ __forceinline__ void mma16816(float c[4], const unsigned a[4], unsigned b0, unsigned b1){
    asm volatile("mma.sync.aligned.m16n8k16.row.col.f32.f16.f16.f32 "
                 "{%0,%1,%2,%3},{%4,%5,%6,%7},{%8,%9},{%0,%1,%2,%3};"
                 : "+f"(c[0]),"+f"(c[1]),"+f"(c[2]),"+f"(c[3])
                 : "r"(a[0]),"r"(a[1]),"r"(a[2]),"r"(a[3]),"r"(b0),"r"(b1));
}

// -------- kernel 1: mask compaction (A: [8192][1024] fp32 -> bitmask) --------
__global__ __launch_bounds__(256) void mask_kernel(const float* __restrict__ A){
    int warp = threadIdx.x >> 5, lane = threadIdx.x & 31;
    int row  = blockIdx.x * 8 + warp;            // 0..8191  (b*N+q)
    const float* a = A + (size_t)row * NN;
    unsigned* mout = g_mask + (size_t)row * 32;
    #pragma unroll 4
    for (int j = 0; j < 32; ++j){
        unsigned m = __ballot_sync(0xffffffffu, a[j*32 + lane] > 0.0f);
        if (lane == 0) mout[j] = m;
    }
}

// -------- fp32 GEMM tile helper: 64 rows x 128 outs per block (256 thr) --------
// thread: tx = tid&31 -> outputs o = 4*tx..4*tx+3 ; ty = tid>>5 -> rows 8*ty..8*ty+7
static __device__ __forceinline__ void gemm_tile(const float (*Xs)[132],
        const float* __restrict__ W, const float* __restrict__ bias,
        int tx, int ty, float y[8][4]){
    unsigned long long acc[4][4];
    #pragma unroll
    for (int rp=0; rp<4; ++rp)
        #pragma unroll
        for (int j=0; j<4; ++j) acc[rp][j] = 0ull;
    for (int k4 = 0; k4 < NF; k4 += 4){
        float w[4][4];
        #pragma unroll
        for (int j=0;j<4;++j) *(float4*)w[j] = *(const float4*)&W[(4*tx+j)*NF + k4];
        float xr[8][4];
        #pragma unroll
        for (int i=0;i<8;++i) *(float4*)xr[i] = *(const float4*)&Xs[ty*8+i][k4];
        #pragma unroll
        for (int kk=0; kk<4; ++kk){
            unsigned long long xp[4], wd[4];
            #pragma unroll
            for (int rp=0; rp<4; ++rp) xp[rp] = pk2(xr[2*rp][kk], xr[2*rp+1][kk]);
            #pragma unroll
            for (int j=0;j<4;++j)      wd[j]  = pk2(w[j][kk],    w[j][kk]);
            #pragma unroll
            for (int rp=0; rp<4; ++rp)
                #pragma unroll
                for (int j=0;j<4;++j)
                    acc[rp][j] = fma2(xp[rp], wd[j], acc[rp][j]);
        }
    }
    float bb[4]; *(float4*)bb = *(const float4*)&bias[4*tx];
    #pragma unroll
    for (int rp=0; rp<4; ++rp)
        #pragma unroll
        for (int j=0;j<4;++j){
            float y0,y1; upk2(acc[rp][j], y0, y1);
            y[2*rp][j]   = y0 + bb[j];
            y[2*rp+1][j] = y1 + bb[j];
        }
}

// -------- kernel 2: fused QKV projection --------
__global__ __launch_bounds__(256) void qkv_kernel(const float* __restrict__ X,
        const float* __restrict__ Wq, const float* __restrict__ bq,
        const float* __restrict__ Wk, const float* __restrict__ bk,
        const float* __restrict__ Wv, const float* __restrict__ bv){
    __shared__ float Xs[64][132];
    int tid = threadIdx.x;
    int row0 = blockIdx.x * 64;                       // global row = b*N+q
    for (int i = tid; i < 2048; i += 256){
        int r = i >> 5, c4 = i & 31;
        *(float4*)&Xs[r][c4*4] = ((const float4*)(X + (size_t)(row0+r)*NF))[c4];
    }
    __syncthreads();
    int tx = tid & 31, ty = tid >> 5;
    int b  = row0 >> 10;
    int q0 = (row0 & (NN-1)) + ty*8;
    float y[8][4];
    // ---- Q (scaled) ----
    gemm_tile(Xs, Wq, bq, tx, ty, y);
    #pragma unroll
    for (int r=0;r<8;++r){
        unsigned u0 = h2(y[r][0]*QSCALE, y[r][1]*QSCALE);
        unsigned u1 = h2(y[r][2]*QSCALE, y[r][3]*QSCALE);
        uint2 u = make_uint2(u0,u1);
        *(uint2*)&g_Q[(size_t)(row0 + ty*8 + r)*NF + 4*tx] = u;
    }
    // ---- K ----
    gemm_tile(Xs, Wk, bk, tx, ty, y);
    #pragma unroll
    for (int r=0;r<8;++r){
        uint2 u = make_uint2(h2(y[r][0],y[r][1]), h2(y[r][2],y[r][3]));
        *(uint2*)&g_K[(size_t)(row0 + ty*8 + r)*NF + 4*tx] = u;
    }
    // ---- V (transposed store: [b][o][q]) ----
    gemm_tile(Xs, Wv, bv, tx, ty, y);
    #pragma unroll
    for (int j=0;j<4;++j){
        int o = 4*tx + j;
        union { __half h[8]; uint4 u; } pk;
        #pragma unroll
        for (int r=0;r<8;++r) pk.h[r] = __float2half(y[r][j]);
        *(uint4*)&g_V[((size_t)(b*NF + o) << 10) + q0] = pk.u;
    }
}

// -------- kernel 3: masked flash attention (no params; uses globals) --------
__global__ __launch_bounds__(256) void attn_kernel(){
    __shared__ unsigned smask[64][33];
    int tid = threadIdx.x;
    int b  = blockIdx.x >> 4;
    int q0 = (blockIdx.x & 15) * 64;
    int h  = tid >> 5, lane = tid & 31;
    for (int i = tid; i < 2048; i += 256){
        int r = i >> 5, w = i & 31;
        smask[r][w] = g_mask[(size_t)((b<<10) + q0 + r)*32 + w];
    }
    __syncthreads();

    int qr = lane >> 2;            // 0..7
    int ms = (lane & 3) * 2;       // col/d offset (even)

    unsigned a[4][4];
    #pragma unroll
    for (int f=0; f<4; ++f){
        const __half* Qp = g_Q + (((size_t)((b<<10) + q0 + f*16 + qr)) << 7) + h*16;
        a[f][0] = *(const unsigned*)(Qp + ms);
        a[f][2] = *(const unsigned*)(Qp + ms + 8);
        const __half* Qp8 = Qp + (8 << 7);
        a[f][1] = *(const unsigned*)(Qp8 + ms);
        a[f][3] = *(const unsigned*)(Qp8 + ms + 8);
    }

    float o[4][2][4];
    float l[4][2];
    #pragma unroll
    for (int f=0;f<4;++f){ l[f][0]=0.f; l[f][1]=0.f;
        #pragma unroll
        for(int t=0;t<2;++t){ o[f][t][0]=0.f;o[f][t][1]=0.f;o[f][t][2]=0.f;o[f][t][3]=0.f; } }

    const __half* Kbase = g_K + (((size_t)(b<<10)) << 7) + h*16;
    const __half* Vbase = g_V + (((size_t)(b*NF + h*16 + qr)) << 10);

    for (int kt = 0; kt < 64; ++kt){
        int kb = kt << 4;
        const __half* Kp = Kbase + (((size_t)(kb + qr)) << 7) + ms;
        unsigned kb0 = *(const unsigned*)Kp;
        unsigned kb1 = *(const unsigned*)(Kp + 8);
        unsigned kb2 = *(const unsigned*)(Kp + (8<<7));
        unsigned kb3 = *(const unsigned*)(Kp + (8<<7) + 8);
        const __half* Vp = Vbase + kb + ms;
        unsigned vb0 = *(const unsigned*)Vp;
        unsigned vb1 = *(const unsigned*)(Vp + 8);
        unsigned vb2 = *(const unsigned*)(Vp + (8<<10));
        unsigned vb3 = *(const unsigned*)(Vp + (8<<10) + 8);
        int w  = kt >> 1;
        int sb = (kt & 1) << 4;
        #pragma unroll
        for (int f=0; f<4; ++f){
            float c0[4] = {0.f,0.f,0.f,0.f};
            float c1[4] = {0.f,0.f,0.f,0.f};
            mma16816(c0, a[f], kb0, kb1);
            mma16816(c1, a[f], kb2, kb3);
            unsigned mlo = smask[f*16 + qr][w]     >> (sb + ms);
            unsigned mhi = smask[f*16 + 8 + qr][w] >> (sb + ms);
            float e00 = ex2f(c0[0]), e01 = ex2f(c0[1]), e02 = ex2f(c0[2]), e03 = ex2f(c0[3]);
            float e10 = ex2f(c1[0]), e11 = ex2f(c1[1]), e12 = ex2f(c1[2]), e13 = ex2f(c1[3]);
            float p00 = (mlo & 1u)   ? e00 : 0.f;
            float p01 = (mlo & 2u)   ? e01 : 0.f;
            float p02 = (mhi & 1u)   ? e02 : 0.f;
            float p03 = (mhi & 2u)   ? e03 : 0.f;
            float p10 = (mlo & 256u) ? e10 : 0.f;
            float p11 = (mlo & 512u) ? e11 : 0.f;
            float p12 = (mhi & 256u) ? e12 : 0.f;
            float p13 = (mhi & 512u) ? e13 : 0.f;
            l[f][0] += (p00 + p01) + (p10 + p11);
            l[f][1] += (p02 + p03) + (p12 + p13);
            unsigned ap[4];
            ap[0] = h2(p00, p01);
            ap[1] = h2(p02, p03);
            ap[2] = h2(p10, p11);
            ap[3] = h2(p12, p13);
            mma16816(o[f][0], ap, vb0, vb1);
            mma16816(o[f][1], ap, vb2, vb3);
        }
    }

    // epilogue: row-sum reduce within quad, normalize, store fp32
    #pragma unroll
    for (int f=0; f<4; ++f){
        float l0 = l[f][0];
        l0 += __shfl_xor_sync(0xffffffffu, l0, 1);
        l0 += __shfl_xor_sync(0xffffffffu, l0, 2);
        float l1 = l[f][1];
        l1 += __shfl_xor_sync(0xffffffffu, l1, 1);
        l1 += __shfl_xor_sync(0xffffffffu, l1, 2);
        float inv0 = rcpf(l0), inv1 = rcpf(l1);
        int rlo = (b<<10) + q0 + f*16 + qr;
        float* Oplo = g_attn + ((size_t)rlo << 7) + h*16 + ms;
        float* Ophi = Oplo + (8 << 7);
        #pragma unroll
        for (int t=0; t<2; ++t){
            float2 vlo = make_float2(o[f][t][0]*inv0, o[f][t][1]*inv0);
            float2 vhi = make_float2(o[f][t][2]*inv1, o[f][t][3]*inv1);
            *(float2*)(Oplo + t*8) = vlo;
            *(float2*)(Ophi + t*8) = vhi;
        }
    }
}

// -------- kernel 4: output projection (g_attn @ Wo.T + bo -> d_out) --------
__global__ __launch_bounds__(256) void out_kernel(const float* __restrict__ Wo,
        const float* __restrict__ bo, float* __restrict__ out){
    __shared__ float Xs[64][132];
    int tid = threadIdx.x;
    int row0 = blockIdx.x * 64;
    for (int i = tid; i < 2048; i += 256){
        int r = i >> 5, c4 = i & 31;
        *(float4*)&Xs[r][c4*4] = ((const float4*)(g_attn + (size_t)(row0+r)*NF))[c4];
    }
    __syncthreads();
    int tx = tid & 31, ty = tid >> 5;
    float y[8][4];
    gemm_tile(Xs, Wo, bo, tx, ty, y);
    #pragma unroll
    for (int r=0;r<8;++r){
        float4 v = make_float4(y[r][0], y[r][1], y[r][2], y[r][3]);
        *(float4*)&out[(size_t)(row0 + ty*8 + r)*NF + 4*tx] = v;
    }
}

// -------- launcher --------
extern "C" void kernel_launch(void* const* d_in, const int* in_sizes, int n_in,
                              void* d_out, int out_size){
    const float* X  = (const float*)d_in[0];
    const float* A  = (const float*)d_in[1];
    const float* Wq = (const float*)d_in[2];
    const float* bq = (const float*)d_in[3];
    const float* Wk = (const float*)d_in[4];
    const float* bk = (const float*)d_in[5];
    const float* Wv = (const float*)d_in[6];
    const float* bv = (const float*)d_in[7];
    const float* Wo = (const float*)d_in[8];
    const float* bo = (const float*)d_in[9];
    float* out = (float*)d_out;

    mask_kernel<<<1024, 256>>>(A);
    qkv_kernel<<<128, 256>>>(X, Wq, bq, Wk, bk, Wv, bv);
    attn_kernel<<<128, 256>>>();
    out_kernel<<<128, 256>>>(Wo, bo, out);
}

// round 4
// speedup vs baseline: 1.4892x; 1.4892x over previous
#include <cuda_runtime.h>
#include <cuda_fp16.h>

#define NB 8
#define NN 1024
#define NF 128
#define NH 8

// -------- scratch (device globals; allocation is forbidden) --------
__device__ __half    g_Q[NB*NN*NF];      // [b*N+q][128], pre-scaled by log2e/4
__device__ __half    g_K[NB*NN*NF];      // [b*N+q][128]
__device__ __half    g_V[NB*NF*NN];      // [b][o=h*16+d][q]  (d-major for PV mma)
__device__ __half    g_attn[NB*NN*NF];   // attention output before Wo (fp16)
__device__ unsigned  g_mask[NB*NN*32];   // [b*N+q][word]; bit j of word w = A[..][w*32+j]>0

#define QSCALE 0.3606737602222409f   // log2(e)/4

// -------- helpers --------
static __device__ __forceinline__ float ex2f(float x){ float r; asm("ex2.approx.ftz.f32 %0,%1;":"=f"(r):"f"(x)); return r; }
static __device__ __forceinline__ float rcpf(float x){ float r; asm("rcp.approx.ftz.f32 %0,%1;":"=f"(r):"f"(x)); return r; }
static __device__ __forceinline__ unsigned h2(float a,float b){
    __half2 h = __floats2half2_rn(a,b); return *reinterpret_cast<unsigned*>(&h); }
static __device__ __forceinline__ void mma16816(float c[4], const unsigned a[4], unsigned b0, unsigned b1){
    asm volatile("mma.sync.aligned.m16n8k16.row.col.f32.f16.f16.f32 "
                 "{%0,%1,%2,%3},{%4,%5,%6,%7},{%8,%9},{%0,%1,%2,%3};"
                 : "+f"(c[0]),"+f"(c[1]),"+f"(c[2]),"+f"(c[3])
                 : "r"(a[0]),"r"(a[1]),"r"(a[2]),"r"(a[3]),"r"(b0),"r"(b1));
}

// -------- kernel 1: mask compaction (A: [8192][1024] fp32 -> bitmask) --------
__global__ __launch_bounds__(256) void mask_kernel(const float* __restrict__ A){
    int warp = threadIdx.x >> 5, lane = threadIdx.x & 31;
    int row  = blockIdx.x * 8 + warp;            // 0..8191  (b*N+q)
    const float* a = A + (size_t)row * NN;
    unsigned* mout = g_mask + (size_t)row * 32;
    #pragma unroll 4
    for (int j = 0; j < 32; ++j){
        unsigned m = __ballot_sync(0xffffffffu, a[j*32 + lane] > 0.0f);
        if (lane == 0) mout[j] = m;
    }
}

// -------- unified HMMA GEMM: Y[128 x 128] = A(128x128) x W(128x128)^T + bias --------
// MODE 0: Q = X Wq^T + bq, *QSCALE, fp16 -> g_Q
// MODE 1: K = X Wk^T + bk, fp16 -> g_K
// MODE 2: V^T = Wv X^T (+bv per row o), fp16 -> g_V [b][o][q]   (A/B roles swapped)
// MODE 3: out = attn Wo^T + bo, fp32 -> d_out
// smem: Xs[128][136] fp16, Ws[128][136] fp16, bias[128] fp32  (dynamic, ~70KB)
template<int MODE>
__global__ __launch_bounds__(256) void gemm_kernel(const float* __restrict__ Xf,
        const float* __restrict__ W, const float* __restrict__ bias,
        float* __restrict__ outf){
    extern __shared__ char smem[];
    __half (*Xs)[136] = (__half(*)[136])smem;                 // 34816 B
    __half (*Ws)[136] = (__half(*)[136])(smem + 34816);       // 34816 B
    float*  bs        = (float*)(smem + 69632);               // 512 B

    const int tid  = threadIdx.x;
    const int row0 = blockIdx.x * 128;      // global row = b*N+q

    // stage A tile (fp32 X -> fp16, or fp16 g_attn copy)
    if (MODE == 3){
        for (int i = tid; i < 4096; i += 256){
            int r = i >> 5, c4 = (i & 31) * 4;
            *(uint2*)&Xs[r][c4] = *(const uint2*)&g_attn[(size_t)(row0 + r)*NF + c4];
        }
    } else {
        for (int i = tid; i < 4096; i += 256){
            int r = i >> 5, c4 = (i & 31) * 4;
            float4 v = *(const float4*)&Xf[(size_t)(row0 + r)*NF + c4];
            uint2 u; u.x = h2(v.x, v.y); u.y = h2(v.z, v.w);
            *(uint2*)&Xs[r][c4] = u;
        }
    }
    // stage W (fp32 -> fp16)
    for (int i = tid; i < 4096; i += 256){
        int r = i >> 5, c4 = (i & 31) * 4;
        float4 v = *(const float4*)&W[(size_t)r*NF + c4];
        uint2 u; u.x = h2(v.x, v.y); u.y = h2(v.z, v.w);
        *(uint2*)&Ws[r][c4] = u;
    }
    if (tid < 128) bs[tid] = bias[tid];
    __syncthreads();

    const int w = tid >> 5, lane = tid & 31;
    const int qr = lane >> 2, lc = lane & 3, ms = lc * 2;

    const unsigned* Abase = (MODE == 2) ? (const unsigned*)Ws : (const unsigned*)Xs;
    const unsigned* Bbase = (MODE == 2) ? (const unsigned*)Xs : (const unsigned*)Ws;

    // A fragments: rows 16w+qr / +8, all 8 k-tiles (row stride 68 words)
    unsigned a[8][4];
    {
        const unsigned* p = Abase + (16*w + qr)*68 + lc;
        #pragma unroll
        for (int kt = 0; kt < 8; ++kt){
            a[kt][0] = p[kt*8];
            a[kt][1] = p[kt*8 + 8*68];
            a[kt][2] = p[kt*8 + 4];
            a[kt][3] = p[kt*8 + 8*68 + 4];
        }
    }

    const int b  = row0 >> 10;
    const int q0 = row0 & (NN - 1);

    #pragma unroll
    for (int g = 0; g < 4; ++g){
        float c[4][4];
        #pragma unroll
        for (int j = 0; j < 4; ++j){ c[j][0]=0.f; c[j][1]=0.f; c[j][2]=0.f; c[j][3]=0.f; }
        #pragma unroll
        for (int kt = 0; kt < 8; ++kt){
            #pragma unroll
            for (int j = 0; j < 4; ++j){
                const unsigned* bp = Bbase + ((g*4 + j)*8 + qr)*68 + kt*8 + lc;
                mma16816(c[j], a[kt], bp[0], bp[4]);
            }
        }
        // epilogue
        #pragma unroll
        for (int j = 0; j < 4; ++j){
            int col = (g*4 + j)*8 + ms;
            if (MODE == 2){
                int o = 16*w + qr;
                float b0 = bs[o], b1 = bs[o + 8];
                __half* dst0 = g_V + (((size_t)(b*NF + o))     << 10) + q0 + col;
                __half* dst1 = g_V + (((size_t)(b*NF + o + 8)) << 10) + q0 + col;
                *(unsigned*)dst0 = h2(c[j][0] + b0, c[j][1] + b0);
                *(unsigned*)dst1 = h2(c[j][2] + b1, c[j][3] + b1);
            } else {
                float b0 = bs[col], b1 = bs[col + 1];
                int r = row0 + 16*w + qr;
                if (MODE == 0){
                    *(unsigned*)&g_Q[(size_t)r*NF + col]     = h2((c[j][0]+b0)*QSCALE, (c[j][1]+b1)*QSCALE);
                    *(unsigned*)&g_Q[(size_t)(r+8)*NF + col] = h2((c[j][2]+b0)*QSCALE, (c[j][3]+b1)*QSCALE);
                } else if (MODE == 1){
                    *(unsigned*)&g_K[(size_t)r*NF + col]     = h2(c[j][0]+b0, c[j][1]+b1);
                    *(unsigned*)&g_K[(size_t)(r+8)*NF + col] = h2(c[j][2]+b0, c[j][3]+b1);
                } else {
                    *(float2*)&outf[(size_t)r*NF + col]     = make_float2(c[j][0]+b0, c[j][1]+b1);
                    *(float2*)&outf[(size_t)(r+8)*NF + col] = make_float2(c[j][2]+b0, c[j][3]+b1);
                }
            }
        }
    }
}

// -------- kernel 3: masked flash attention (no params; uses globals) --------
__global__ __launch_bounds__(256) void attn_kernel(){
    __shared__ unsigned smask[64][33];
    int tid = threadIdx.x;
    int b  = blockIdx.x >> 4;
    int q0 = (blockIdx.x & 15) * 64;
    int h  = tid >> 5, lane = tid & 31;
    for (int i = tid; i < 2048; i += 256){
        int r = i >> 5, w = i & 31;
        smask[r][w] = g_mask[(size_t)((b<<10) + q0 + r)*32 + w];
    }
    __syncthreads();

    int qr = lane >> 2;            // 0..7
    int ms = (lane & 3) * 2;       // col/d offset (even)

    unsigned a[4][4];
    #pragma unroll
    for (int f=0; f<4; ++f){
        const __half* Qp = g_Q + (((size_t)((b<<10) + q0 + f*16 + qr)) << 7) + h*16;
        a[f][0] = *(const unsigned*)(Qp + ms);
        a[f][2] = *(const unsigned*)(Qp + ms + 8);
        const __half* Qp8 = Qp + (8 << 7);
        a[f][1] = *(const unsigned*)(Qp8 + ms);
        a[f][3] = *(const unsigned*)(Qp8 + ms + 8);
    }

    float o[4][2][4];
    float l[4][2];
    #pragma unroll
    for (int f=0;f<4;++f){ l[f][0]=0.f; l[f][1]=0.f;
        #pragma unroll
        for(int t=0;t<2;++t){ o[f][t][0]=0.f;o[f][t][1]=0.f;o[f][t][2]=0.f;o[f][t][3]=0.f; } }

    const __half* Kbase = g_K + (((size_t)(b<<10)) << 7) + h*16;
    const __half* Vbase = g_V + (((size_t)(b*NF + h*16 + qr)) << 10);

    for (int kt = 0; kt < 64; ++kt){
        int kb = kt << 4;
        const __half* Kp = Kbase + (((size_t)(kb + qr)) << 7) + ms;
        unsigned kb0 = *(const unsigned*)Kp;
        unsigned kb1 = *(const unsigned*)(Kp + 8);
        unsigned kb2 = *(const unsigned*)(Kp + (8<<7));
        unsigned kb3 = *(const unsigned*)(Kp + (8<<7) + 8);
        const __half* Vp = Vbase + kb + ms;
        unsigned vb0 = *(const unsigned*)Vp;
        unsigned vb1 = *(const unsigned*)(Vp + 8);
        unsigned vb2 = *(const unsigned*)(Vp + (8<<10));
        unsigned vb3 = *(const unsigned*)(Vp + (8<<10) + 8);
        int w  = kt >> 1;
        int sb = (kt & 1) << 4;
        #pragma unroll
        for (int f=0; f<4; ++f){
            float c0[4] = {0.f,0.f,0.f,0.f};
            float c1[4] = {0.f,0.f,0.f,0.f};
            mma16816(c0, a[f], kb0, kb1);
            mma16816(c1, a[f], kb2, kb3);
            unsigned mlo = smask[f*16 + qr][w]     >> (sb + ms);
            unsigned mhi = smask[f*16 + 8 + qr][w] >> (sb + ms);
            float e00 = ex2f(c0[0]), e01 = ex2f(c0[1]), e02 = ex2f(c0[2]), e03 = ex2f(c0[3]);
            float e10 = ex2f(c1[0]), e11 = ex2f(c1[1]), e12 = ex2f(c1[2]), e13 = ex2f(c1[3]);
            float p00 = (mlo & 1u)   ? e00 : 0.f;
            float p01 = (mlo & 2u)   ? e01 : 0.f;
            float p02 = (mhi & 1u)   ? e02 : 0.f;
            float p03 = (mhi & 2u)   ? e03 : 0.f;
            float p10 = (mlo & 256u) ? e10 : 0.f;
            float p11 = (mlo & 512u) ? e11 : 0.f;
            float p12 = (mhi & 256u) ? e12 : 0.f;
            float p13 = (mhi & 512u) ? e13 : 0.f;
            l[f][0] += (p00 + p01) + (p10 + p11);
            l[f][1] += (p02 + p03) + (p12 + p13);
            unsigned ap[4];
            ap[0] = h2(p00, p01);
            ap[1] = h2(p02, p03);
            ap[2] = h2(p10, p11);
            ap[3] = h2(p12, p13);
            mma16816(o[f][0], ap, vb0, vb1);
            mma16816(o[f][1], ap, vb2, vb3);
        }
    }

    // epilogue: row-sum reduce within quad, normalize, store fp16 (packed)
    #pragma unroll
    for (int f=0; f<4; ++f){
        float l0 = l[f][0];
        l0 += __shfl_xor_sync(0xffffffffu, l0, 1);
        l0 += __shfl_xor_sync(0xffffffffu, l0, 2);
        float l1 = l[f][1];
        l1 += __shfl_xor_sync(0xffffffffu, l1, 1);
        l1 += __shfl_xor_sync(0xffffffffu, l1, 2);
        float inv0 = rcpf(l0), inv1 = rcpf(l1);
        int rlo = (b<<10) + q0 + f*16 + qr;
        __half* Oplo = g_attn + ((size_t)rlo << 7) + h*16 + ms;
        __half* Ophi = Oplo + (8 << 7);
        #pragma unroll
        for (int t=0; t<2; ++t){
            *(unsigned*)(Oplo + t*8) = h2(o[f][t][0]*inv0, o[f][t][1]*inv0);
            *(unsigned*)(Ophi + t*8) = h2(o[f][t][2]*inv1, o[f][t][3]*inv1);
        }
    }
}

// -------- launcher --------
extern "C" void kernel_launch(void* const* d_in, const int* in_sizes, int n_in,
                              void* d_out, int out_size){
    const float* X  = (const float*)d_in[0];
    const float* A  = (const float*)d_in[1];
    const float* Wq = (const float*)d_in[2];
    const float* bq = (const float*)d_in[3];
    const float* Wk = (const float*)d_in[4];
    const float* bk = (const float*)d_in[5];
    const float* Wv = (const float*)d_in[6];
    const float* bv = (const float*)d_in[7];
    const float* Wo = (const float*)d_in[8];
    const float* bo = (const float*)d_in[9];
    float* out = (float*)d_out;

    const int SMEM = 70144;
    cudaFuncSetAttribute(gemm_kernel<0>, cudaFuncAttributeMaxDynamicSharedMemorySize, SMEM);
    cudaFuncSetAttribute(gemm_kernel<1>, cudaFuncAttributeMaxDynamicSharedMemorySize, SMEM);
    cudaFuncSetAttribute(gemm_kernel<2>, cudaFuncAttributeMaxDynamicSharedMemorySize, SMEM);
    cudaFuncSetAttribute(gemm_kernel<3>, cudaFuncAttributeMaxDynamicSharedMemorySize, SMEM);

    mask_kernel<<<1024, 256>>>(A);
    gemm_kernel<0><<<64, 256, SMEM>>>(X, Wq, bq, nullptr);
    gemm_kernel<1><<<64, 256, SMEM>>>(X, Wk, bk, nullptr);
    gemm_kernel<2><<<64, 256, SMEM>>>(X, Wv, bv, nullptr);
    attn_kernel<<<128, 256>>>();
    gemm_kernel<3><<<64, 256, SMEM>>>(nullptr, Wo, bo, out);
}

// round 5
// speedup vs baseline: 1.7762x; 1.1928x over previous
#include <cuda_runtime.h>
#include <cuda_fp16.h>

#define NB 8
#define NN 1024
#define NF 128
#define NH 8

// -------- scratch (device globals; allocation is forbidden) --------
__device__ __half    g_Q[NB*NN*NF];      // [b*N+q][128], pre-scaled by log2e/4
__device__ __half    g_K[NB*NN*NF];      // [b*N+q][128]
__device__ __half    g_V[NB*NF*NN];      // [b][o=h*16+d][q]  (d-major for PV mma)
__device__ unsigned  g_mask[NB*NN*32];   // [b*N+q][word]; bit j of word w = A[..][w*32+j]>0

#define QSCALE 0.3606737602222409f   // log2(e)/4
#define ONES2  0x3C003C00u           // half2(1,1)

// -------- helpers --------
static __device__ __forceinline__ float rcpf(float x){ float r; asm("rcp.approx.ftz.f32 %0,%1;":"=f"(r):"f"(x)); return r; }
static __device__ __forceinline__ unsigned h2(float a,float b){
    __half2 h = __floats2half2_rn(a,b); return *reinterpret_cast<unsigned*>(&h); }
static __device__ __forceinline__ unsigned hex2(unsigned x){
    unsigned r; asm("ex2.approx.f16x2 %0,%1;":"=r"(r):"r"(x)); return r; }
// expand low 2 bits -> per-half 0xFFFF masks (bit0 -> low half, bit1 -> high half)
static __device__ __forceinline__ unsigned mpat(unsigned bits){
    unsigned t = (bits & 3u) * 0x4080u;   // bit0->bit7 (byte0 msb), bit1->bit15 (byte1 msb)
    unsigned r; asm("prmt.b32 %0,%1,%2,%3;":"=r"(r):"r"(t),"r"(0u),"r"(0x9988u));
    return r;                              // bytes0,1=sign(byte0), bytes2,3=sign(byte1)
}
static __device__ __forceinline__ void mma16816(float c[4], const unsigned a[4], unsigned b0, unsigned b1){
    asm volatile("mma.sync.aligned.m16n8k16.row.col.f32.f16.f16.f32 "
                 "{%0,%1,%2,%3},{%4,%5,%6,%7},{%8,%9},{%0,%1,%2,%3};"
                 : "+f"(c[0]),"+f"(c[1]),"+f"(c[2]),"+f"(c[3])
                 : "r"(a[0]),"r"(a[1]),"r"(a[2]),"r"(a[3]),"r"(b0),"r"(b1));
}

// ============ kernel 1: fused mask compaction + Q/K/V projections ============
// blocks 0..191: GEMM (mode = bid/64: 0=Q,1=K,2=V^T), 512 threads, 128x128 tile
// blocks 192..703: mask ballot (16 rows per block, warp per row)
__global__ __launch_bounds__(512) void pre_kernel(const float* __restrict__ X,
        const float* __restrict__ A,
        const float* __restrict__ Wq, const float* __restrict__ bq,
        const float* __restrict__ Wk, const float* __restrict__ bk,
        const float* __restrict__ Wv, const float* __restrict__ bv){
    int bid = blockIdx.x;
    int tid = threadIdx.x;
    int w = tid >> 5, lane = tid & 31;

    if (bid >= 192){
        // ---- mask part ----
        int row = (bid - 192) * 16 + w;               // 0..8191 (b*N+q)
        const float* a = A + (size_t)row * NN;
        unsigned myw = 0;
        #pragma unroll
        for (int j = 0; j < 32; ++j){
            unsigned m = __ballot_sync(0xffffffffu, a[j*32 + lane] > 0.0f);
            if (lane == j) myw = m;
        }
        g_mask[(size_t)row * 32 + lane] = myw;
        return;
    }

    // ---- GEMM part ----
    extern __shared__ char smem[];
    __half (*Xs)[136] = (__half(*)[136])smem;              // 34816 B
    __half (*Ws)[136] = (__half(*)[136])(smem + 34816);    // 34816 B
    float*  bs        = (float*)(smem + 69632);            // 512 B

    int mode = bid >> 6;        // 0=Q 1=K 2=V
    int tile = bid & 63;
    const float* Wp = (mode == 0) ? Wq : (mode == 1) ? Wk : Wv;
    const float* bp = (mode == 0) ? bq : (mode == 1) ? bk : bv;
    int row0 = tile * 128;

    for (int i = tid; i < 4096; i += 512){
        int r = i >> 5, c4 = (i & 31) * 4;
        float4 v = *(const float4*)&X[(size_t)(row0 + r)*NF + c4];
        uint2 u; u.x = h2(v.x, v.y); u.y = h2(v.z, v.w);
        *(uint2*)&Xs[r][c4] = u;
        float4 ww = *(const float4*)&Wp[(size_t)r*NF + c4];
        uint2 uw; uw.x = h2(ww.x, ww.y); uw.y = h2(ww.z, ww.w);
        *(uint2*)&Ws[r][c4] = uw;
    }
    if (tid < 128) bs[tid] = bp[tid];
    __syncthreads();

    int qr = lane >> 2, lc = lane & 3, ms = lc * 2;
    int rg = w >> 1, ch = w & 1;

    const unsigned* Ab = (mode == 2) ? (const unsigned*)Ws : (const unsigned*)Xs;
    const unsigned* Bb = (mode == 2) ? (const unsigned*)Xs : (const unsigned*)Ws;

    unsigned a[8][4];
    {
        const unsigned* p = Ab + (16*rg + qr)*68 + lc;
        #pragma unroll
        for (int kt = 0; kt < 8; ++kt){
            a[kt][0] = p[kt*8];
            a[kt][1] = p[kt*8 + 8*68];
            a[kt][2] = p[kt*8 + 4];
            a[kt][3] = p[kt*8 + 8*68 + 4];
        }
    }

    float c[8][4];
    #pragma unroll
    for (int j = 0; j < 8; ++j){ c[j][0]=0.f; c[j][1]=0.f; c[j][2]=0.f; c[j][3]=0.f; }
    #pragma unroll
    for (int j = 0; j < 8; ++j){
        const unsigned* bpq = Bb + (64*ch + 8*j + qr)*68 + lc;
        #pragma unroll
        for (int kt = 0; kt < 8; ++kt)
            mma16816(c[j], a[kt], bpq[kt*8], bpq[kt*8 + 4]);
    }

    int b = row0 >> 10, q0 = row0 & (NN - 1);
    #pragma unroll
    for (int j = 0; j < 8; ++j){
        if (mode == 2){
            int o0 = 16*rg + qr, o1 = o0 + 8;
            int qc = 64*ch + 8*j + ms;
            float b0 = bs[o0], b1 = bs[o1];
            *(unsigned*)&g_V[(((size_t)(b*NF + o0)) << 10) + q0 + qc] = h2(c[j][0]+b0, c[j][1]+b0);
            *(unsigned*)&g_V[(((size_t)(b*NF + o1)) << 10) + q0 + qc] = h2(c[j][2]+b1, c[j][3]+b1);
        } else {
            int col = 64*ch + 8*j + ms;
            float b0 = bs[col], b1 = bs[col + 1];
            int r = row0 + 16*rg + qr;
            if (mode == 0){
                *(unsigned*)&g_Q[(size_t)r*NF + col]     = h2((c[j][0]+b0)*QSCALE, (c[j][1]+b1)*QSCALE);
                *(unsigned*)&g_Q[(size_t)(r+8)*NF + col] = h2((c[j][2]+b0)*QSCALE, (c[j][3]+b1)*QSCALE);
            } else {
                *(unsigned*)&g_K[(size_t)r*NF + col]     = h2(c[j][0]+b0, c[j][1]+b1);
                *(unsigned*)&g_K[(size_t)(r+8)*NF + col] = h2(c[j][2]+b0, c[j][3]+b1);
            }
        }
    }
}

// ============ kernel 2: masked flash attention + fused output projection ============
// grid 128 (b,q0-tile of 64), 256 threads (warp = head)
// smem: Wos[128][136]h @0, Xs[64][136]h @34816, smask[64][33]u32 @52224, bs[128]f @60672
__global__ __launch_bounds__(256) void attn_kernel(const float* __restrict__ Wo,
        const float* __restrict__ bo, float* __restrict__ out){
    extern __shared__ char smem[];
    __half   (*Wos)[136]  = (__half(*)[136])smem;
    __half   (*Xs)[136]   = (__half(*)[136])(smem + 34816);
    unsigned (*smask)[33] = (unsigned(*)[33])(smem + 52224);
    float*    bs          = (float*)(smem + 60672);

    int tid = threadIdx.x;
    int b  = blockIdx.x >> 4;
    int q0 = (blockIdx.x & 15) * 64;
    int h  = tid >> 5, lane = tid & 31;

    // stage Wo (fp32->fp16), bias, mask
    for (int i = tid; i < 4096; i += 256){
        int r = i >> 5, c4 = (i & 31) * 4;
        float4 v = *(const float4*)&Wo[(size_t)r*NF + c4];
        uint2 u; u.x = h2(v.x, v.y); u.y = h2(v.z, v.w);
        *(uint2*)&Wos[r][c4] = u;
    }
    if (tid < 128) bs[tid] = bo[tid];
    for (int i = tid; i < 2048; i += 256){
        int r = i >> 5, ww = i & 31;
        smask[r][ww] = g_mask[(size_t)((b<<10) + q0 + r)*32 + ww];
    }
    __syncthreads();

    int qr = lane >> 2;            // 0..7
    int lc = lane & 3;
    int ms = lc * 2;

    unsigned a[4][4];
    #pragma unroll
    for (int f=0; f<4; ++f){
        const __half* Qp = g_Q + (((size_t)((b<<10) + q0 + f*16 + qr)) << 7) + h*16;
        a[f][0] = *(const unsigned*)(Qp + ms);
        a[f][2] = *(const unsigned*)(Qp + ms + 8);
        const __half* Qp8 = Qp + (8 << 7);
        a[f][1] = *(const unsigned*)(Qp8 + ms);
        a[f][3] = *(const unsigned*)(Qp8 + ms + 8);
    }

    float o[4][2][4];
    float lsum[4][4];
    #pragma unroll
    for (int f=0;f<4;++f){
        #pragma unroll
        for (int j=0;j<4;++j) lsum[f][j]=0.f;
        #pragma unroll
        for (int t=0;t<2;++t){ o[f][t][0]=0.f;o[f][t][1]=0.f;o[f][t][2]=0.f;o[f][t][3]=0.f; }
    }

    const __half* Kbase = g_K + (((size_t)(b<<10)) << 7) + h*16;
    const __half* Vbase = g_V + (((size_t)(b*NF + h*16 + qr)) << 10);

    for (int kt = 0; kt < 64; ++kt){
        int kb = kt << 4;
        const __half* Kp = Kbase + (((size_t)(kb + qr)) << 7) + ms;
        unsigned kb0 = *(const unsigned*)Kp;
        unsigned kb1 = *(const unsigned*)(Kp + 8);
        unsigned kb2 = *(const unsigned*)(Kp + (8<<7));
        unsigned kb3 = *(const unsigned*)(Kp + (8<<7) + 8);
        const __half* Vp = Vbase + kb + ms;
        unsigned vb0 = *(const unsigned*)Vp;
        unsigned vb1 = *(const unsigned*)(Vp + 8);
        unsigned vb2 = *(const unsigned*)(Vp + (8<<10));
        unsigned vb3 = *(const unsigned*)(Vp + (8<<10) + 8);
        int ww   = kt >> 1;
        int sbms = ((kt & 1) << 4) + ms;
        #pragma unroll
        for (int f=0; f<4; ++f){
            float c0[4] = {0.f,0.f,0.f,0.f};
            float c1[4] = {0.f,0.f,0.f,0.f};
            mma16816(c0, a[f], kb0, kb1);
            mma16816(c1, a[f], kb2, kb3);
            unsigned mlo = smask[f*16 + qr][ww]     >> sbms;
            unsigned mhi = smask[f*16 + 8 + qr][ww] >> sbms;
            unsigned ap[4];
            ap[0] = hex2(h2(c0[0], c0[1])) & mpat(mlo);
            ap[1] = hex2(h2(c0[2], c0[3])) & mpat(mhi);
            ap[2] = hex2(h2(c1[0], c1[1])) & mpat(mlo >> 8);
            ap[3] = hex2(h2(c1[2], c1[3])) & mpat(mhi >> 8);
            mma16816(o[f][0], ap, vb0, vb1);
            mma16816(o[f][1], ap, vb2, vb3);
            mma16816(lsum[f], ap, ONES2, ONES2);
        }
    }

    // normalize and stage attn output tile (fp16) to smem
    #pragma unroll
    for (int f=0; f<4; ++f){
        float inv0 = rcpf(lsum[f][0]);
        float inv1 = rcpf(lsum[f][2]);
        #pragma unroll
        for (int t=0; t<2; ++t){
            *(unsigned*)&Xs[f*16 + qr][h*16 + t*8 + ms]     = h2(o[f][t][0]*inv0, o[f][t][1]*inv0);
            *(unsigned*)&Xs[f*16 + 8 + qr][h*16 + t*8 + ms] = h2(o[f][t][2]*inv1, o[f][t][3]*inv1);
        }
    }
    __syncthreads();

    // ---- fused output projection: out(64x128) = Xs @ Wos^T + bo ----
    int rg = h >> 1, ch = h & 1;   // rg 0..3 row group, ch col half
    unsigned a2[8][4];
    {
        const unsigned* p = (const unsigned*)Xs + (16*rg + qr)*68 + lc;
        #pragma unroll
        for (int kt = 0; kt < 8; ++kt){
            a2[kt][0] = p[kt*8];
            a2[kt][1] = p[kt*8 + 8*68];
            a2[kt][2] = p[kt*8 + 4];
            a2[kt][3] = p[kt*8 + 8*68 + 4];
        }
    }
    #pragma unroll
    for (int j = 0; j < 8; ++j){
        float c[4] = {0.f,0.f,0.f,0.f};
        const unsigned* bp = (const unsigned*)Wos + (64*ch + 8*j + qr)*68 + lc;
        #pragma unroll
        for (int kt = 0; kt < 8; ++kt)
            mma16816(c, a2[kt], bp[kt*8], bp[kt*8 + 4]);
        int col = 64*ch + 8*j + ms;
        float b0 = bs[col], b1 = bs[col + 1];
        int r = (b<<10) + q0 + 16*rg + qr;
        *(float2*)&out[(size_t)r*NF + col]     = make_float2(c[0]+b0, c[1]+b1);
        *(float2*)&out[(size_t)(r+8)*NF + col] = make_float2(c[2]+b0, c[3]+b1);
    }
}

// -------- launcher --------
extern "C" void kernel_launch(void* const* d_in, const int* in_sizes, int n_in,
                              void* d_out, int out_size){
    const float* X  = (const float*)d_in[0];
    const float* A  = (const float*)d_in[1];
    const float* Wq = (const float*)d_in[2];
    const float* bq = (const float*)d_in[3];
    const float* Wk = (const float*)d_in[4];
    const float* bk = (const float*)d_in[5];
    const float* Wv = (const float*)d_in[6];
    const float* bv = (const float*)d_in[7];
    const float* Wo = (const float*)d_in[8];
    const float* bo = (const float*)d_in[9];
    float* out = (float*)d_out;

    const int SMEM1 = 70144;
    const int SMEM2 = 61184;
    cudaFuncSetAttribute(pre_kernel,  cudaFuncAttributeMaxDynamicSharedMemorySize, SMEM1);
    cudaFuncSetAttribute(attn_kernel, cudaFuncAttributeMaxDynamicSharedMemorySize, SMEM2);

    pre_kernel<<<704, 512, SMEM1>>>(X, A, Wq, bq, Wk, bk, Wv, bv);
    attn_kernel<<<128, 256, SMEM2>>>(Wo, bo, out);
}

// round 6
// speedup vs baseline: 2.1886x; 1.2322x over previous
#include <cuda_runtime.h>
#include <cuda_fp16.h>

#define NB 8
#define NN 1024
#define NF 128
#define NH 8

// -------- scratch (device globals; allocation is forbidden) --------
__device__ __half    g_Q[NB*NN*NF];      // [b*N+q][128], pre-scaled by log2e/4
__device__ __half    g_K[NB*NN*NF];      // [b*N+q][128]
__device__ __half    g_V[NB*NF*NN];      // [b][o=h*16+d][q]  (d-major for PV mma)
__device__ unsigned  g_mask[NB*NN*32];   // [b*N+q][word]; bit j of word w = A[..][w*32+j]>0

#define QSCALE 0.3606737602222409f   // log2(e)/4
#define ONES2  0x3C003C00u           // half2(1,1)

// -------- helpers --------
static __device__ __forceinline__ float rcpf(float x){ float r; asm("rcp.approx.ftz.f32 %0,%1;":"=f"(r):"f"(x)); return r; }
static __device__ __forceinline__ unsigned h2(float a,float b){
    __half2 h = __floats2half2_rn(a,b); return *reinterpret_cast<unsigned*>(&h); }
static __device__ __forceinline__ unsigned hex2(unsigned x){
    unsigned r; asm("ex2.approx.f16x2 %0,%1;":"=r"(r):"r"(x)); return r; }
// expand low 2 bits -> per-half 0xFFFF masks (bit0 -> low half, bit1 -> high half)
static __device__ __forceinline__ unsigned mpat(unsigned bits){
    unsigned t = (bits & 3u) * 0x4080u;   // bit0->bit7 (byte0 msb), bit1->bit15 (byte1 msb)
    unsigned r; asm("prmt.b32 %0,%1,%2,%3;":"=r"(r):"r"(t),"r"(0u),"r"(0x9988u));
    return r;                              // bytes0,1=sign(byte0), bytes2,3=sign(byte1)
}
static __device__ __forceinline__ void mma16816(float c[4], const unsigned a[4], unsigned b0, unsigned b1){
    asm volatile("mma.sync.aligned.m16n8k16.row.col.f32.f16.f16.f32 "
                 "{%0,%1,%2,%3},{%4,%5,%6,%7},{%8,%9},{%0,%1,%2,%3};"
                 : "+f"(c[0]),"+f"(c[1]),"+f"(c[2]),"+f"(c[3])
                 : "r"(a[0]),"r"(a[1]),"r"(a[2]),"r"(a[3]),"r"(b0),"r"(b1));
}

// ============ kernel 1: fused mask compaction + Q/K/V projections ============
// blocks 0..191: GEMM (mode = bid/64: 0=Q,1=K,2=V^T), 512 threads, 128x128 tile
// blocks 192..703: mask ballot (16 rows per block, warp per row)
__global__ __launch_bounds__(512) void pre_kernel(const float* __restrict__ X,
        const float* __restrict__ A,
        const float* __restrict__ Wq, const float* __restrict__ bq,
        const float* __restrict__ Wk, const float* __restrict__ bk,
        const float* __restrict__ Wv, const float* __restrict__ bv){
    int bid = blockIdx.x;
    int tid = threadIdx.x;
    int w = tid >> 5, lane = tid & 31;

    if (bid >= 192){
        // ---- mask part ----
        int row = (bid - 192) * 16 + w;               // 0..8191 (b*N+q)
        const float* a = A + (size_t)row * NN;
        unsigned myw = 0;
        #pragma unroll
        for (int j = 0; j < 32; ++j){
            unsigned m = __ballot_sync(0xffffffffu, a[j*32 + lane] > 0.0f);
            if (lane == j) myw = m;
        }
        g_mask[(size_t)row * 32 + lane] = myw;
        return;
    }

    // ---- GEMM part ----
    extern __shared__ char smem[];
    __half (*Xs)[136] = (__half(*)[136])smem;              // 34816 B
    __half (*Ws)[136] = (__half(*)[136])(smem + 34816);    // 34816 B
    float*  bs        = (float*)(smem + 69632);            // 512 B

    int mode = bid >> 6;        // 0=Q 1=K 2=V
    int tile = bid & 63;
    const float* Wp = (mode == 0) ? Wq : (mode == 1) ? Wk : Wv;
    const float* bp = (mode == 0) ? bq : (mode == 1) ? bk : bv;
    int row0 = tile * 128;

    for (int i = tid; i < 4096; i += 512){
        int r = i >> 5, c4 = (i & 31) * 4;
        float4 v = *(const float4*)&X[(size_t)(row0 + r)*NF + c4];
        uint2 u; u.x = h2(v.x, v.y); u.y = h2(v.z, v.w);
        *(uint2*)&Xs[r][c4] = u;
        float4 ww = *(const float4*)&Wp[(size_t)r*NF + c4];
        uint2 uw; uw.x = h2(ww.x, ww.y); uw.y = h2(ww.z, ww.w);
        *(uint2*)&Ws[r][c4] = uw;
    }
    if (tid < 128) bs[tid] = bp[tid];
    __syncthreads();

    int qr = lane >> 2, lc = lane & 3, ms = lc * 2;
    int rg = w >> 1, ch = w & 1;

    const unsigned* Ab = (mode == 2) ? (const unsigned*)Ws : (const unsigned*)Xs;
    const unsigned* Bb = (mode == 2) ? (const unsigned*)Xs : (const unsigned*)Ws;

    unsigned a[8][4];
    {
        const unsigned* p = Ab + (16*rg + qr)*68 + lc;
        #pragma unroll
        for (int kt = 0; kt < 8; ++kt){
            a[kt][0] = p[kt*8];
            a[kt][1] = p[kt*8 + 8*68];
            a[kt][2] = p[kt*8 + 4];
            a[kt][3] = p[kt*8 + 8*68 + 4];
        }
    }

    float c[8][4];
    #pragma unroll
    for (int j = 0; j < 8; ++j){ c[j][0]=0.f; c[j][1]=0.f; c[j][2]=0.f; c[j][3]=0.f; }
    #pragma unroll
    for (int j = 0; j < 8; ++j){
        const unsigned* bpq = Bb + (64*ch + 8*j + qr)*68 + lc;
        #pragma unroll
        for (int kt = 0; kt < 8; ++kt)
            mma16816(c[j], a[kt], bpq[kt*8], bpq[kt*8 + 4]);
    }

    int b = row0 >> 10, q0 = row0 & (NN - 1);
    #pragma unroll
    for (int j = 0; j < 8; ++j){
        if (mode == 2){
            int o0 = 16*rg + qr, o1 = o0 + 8;
            int qc = 64*ch + 8*j + ms;
            float b0 = bs[o0], b1 = bs[o1];
            *(unsigned*)&g_V[(((size_t)(b*NF + o0)) << 10) + q0 + qc] = h2(c[j][0]+b0, c[j][1]+b0);
            *(unsigned*)&g_V[(((size_t)(b*NF + o1)) << 10) + q0 + qc] = h2(c[j][2]+b1, c[j][3]+b1);
        } else {
            int col = 64*ch + 8*j + ms;
            float b0 = bs[col], b1 = bs[col + 1];
            int r = row0 + 16*rg + qr;
            if (mode == 0){
                *(unsigned*)&g_Q[(size_t)r*NF + col]     = h2((c[j][0]+b0)*QSCALE, (c[j][1]+b1)*QSCALE);
                *(unsigned*)&g_Q[(size_t)(r+8)*NF + col] = h2((c[j][2]+b0)*QSCALE, (c[j][3]+b1)*QSCALE);
            } else {
                *(unsigned*)&g_K[(size_t)r*NF + col]     = h2(c[j][0]+b0, c[j][1]+b1);
                *(unsigned*)&g_K[(size_t)(r+8)*NF + col] = h2(c[j][2]+b0, c[j][3]+b1);
            }
        }
    }
}

// ============ kernel 2: masked flash attention + fused output projection ============
// grid 128 (b, q0-tile of 64), 512 threads: warp = (half, head); h = wid&7, half = wid>>3
// each warp: 32 query rows (2 mma fragments), all 1024 keys, K/V software-pipelined
// smem: Wos[128][136]h @0, Xs[64][136]h @34816, smask[64][33]u32 @52224, bs[128]f @60672
__global__ __launch_bounds__(512) void attn_kernel(const float* __restrict__ Wo,
        const float* __restrict__ bo, float* __restrict__ out){
    extern __shared__ char smem[];
    __half   (*Wos)[136]  = (__half(*)[136])smem;
    __half   (*Xs)[136]   = (__half(*)[136])(smem + 34816);
    unsigned (*smask)[33] = (unsigned(*)[33])(smem + 52224);
    float*    bs          = (float*)(smem + 60672);

    int tid = threadIdx.x;
    int b  = blockIdx.x >> 4;
    int q0 = (blockIdx.x & 15) * 64;
    int wid = tid >> 5, lane = tid & 31;
    int h = wid & 7, half = wid >> 3;

    // stage Wo (fp32->fp16), bias, mask
    for (int i = tid; i < 4096; i += 512){
        int r = i >> 5, c4 = (i & 31) * 4;
        float4 v = *(const float4*)&Wo[(size_t)r*NF + c4];
        uint2 u; u.x = h2(v.x, v.y); u.y = h2(v.z, v.w);
        *(uint2*)&Wos[r][c4] = u;
    }
    if (tid < 128) bs[tid] = bo[tid];
    for (int i = tid; i < 2048; i += 512){
        int r = i >> 5, ww = i & 31;
        smask[r][ww] = g_mask[(size_t)((b<<10) + q0 + r)*32 + ww];
    }
    __syncthreads();

    int qr = lane >> 2;            // 0..7
    int lc = lane & 3;
    int ms = lc * 2;
    int rbase = 32*half;           // local q-row base for this warp

    unsigned a[2][4];
    #pragma unroll
    for (int f=0; f<2; ++f){
        const __half* Qp = g_Q + (((size_t)((b<<10) + q0 + rbase + f*16 + qr)) << 7) + h*16;
        a[f][0] = *(const unsigned*)(Qp + ms);
        a[f][2] = *(const unsigned*)(Qp + ms + 8);
        const __half* Qp8 = Qp + (8 << 7);
        a[f][1] = *(const unsigned*)(Qp8 + ms);
        a[f][3] = *(const unsigned*)(Qp8 + ms + 8);
    }

    float o[2][2][4];
    float lsum[2][4];
    #pragma unroll
    for (int f=0;f<2;++f){
        #pragma unroll
        for (int j=0;j<4;++j) lsum[f][j]=0.f;
        #pragma unroll
        for (int t=0;t<2;++t){ o[f][t][0]=0.f;o[f][t][1]=0.f;o[f][t][2]=0.f;o[f][t][3]=0.f; }
    }

    const __half* Kbase = g_K + (((size_t)(b<<10)) << 7) + h*16 + ms;
    const __half* Vbase = g_V + (((size_t)(b*NF + h*16 + qr)) << 10) + ms;

    // preload kt=0
    unsigned kb0, kb1, kb2, kb3, vb0, vb1, vb2, vb3;
    {
        const __half* Kp = Kbase + (((size_t)qr) << 7);
        kb0 = *(const unsigned*)Kp;
        kb1 = *(const unsigned*)(Kp + 8);
        kb2 = *(const unsigned*)(Kp + (8<<7));
        kb3 = *(const unsigned*)(Kp + (8<<7) + 8);
        const __half* Vp = Vbase;
        vb0 = *(const unsigned*)Vp;
        vb1 = *(const unsigned*)(Vp + 8);
        vb2 = *(const unsigned*)(Vp + (8<<10));
        vb3 = *(const unsigned*)(Vp + (8<<10) + 8);
    }

    for (int kt = 0; kt < 64; ++kt){
        // ---- prefetch kt+1 (wrapped; last-iter loads are discarded L1 hits) ----
        int nkt = (kt + 1) & 63;
        unsigned nk0, nk1, nk2, nk3, nv0, nv1, nv2, nv3;
        {
            const __half* Kp = Kbase + (((size_t)((nkt<<4) + qr)) << 7);
            nk0 = *(const unsigned*)Kp;
            nk1 = *(const unsigned*)(Kp + 8);
            nk2 = *(const unsigned*)(Kp + (8<<7));
            nk3 = *(const unsigned*)(Kp + (8<<7) + 8);
            const __half* Vp = Vbase + (nkt<<4);
            nv0 = *(const unsigned*)Vp;
            nv1 = *(const unsigned*)(Vp + 8);
            nv2 = *(const unsigned*)(Vp + (8<<10));
            nv3 = *(const unsigned*)(Vp + (8<<10) + 8);
        }
        // ---- compute current kt ----
        int ww   = kt >> 1;
        int sbms = ((kt & 1) << 4) + ms;
        #pragma unroll
        for (int f=0; f<2; ++f){
            float c0[4] = {0.f,0.f,0.f,0.f};
            float c1[4] = {0.f,0.f,0.f,0.f};
            mma16816(c0, a[f], kb0, kb1);
            mma16816(c1, a[f], kb2, kb3);
            unsigned mlo = smask[rbase + f*16 + qr][ww]     >> sbms;
            unsigned mhi = smask[rbase + f*16 + 8 + qr][ww] >> sbms;
            unsigned ap[4];
            ap[0] = hex2(h2(c0[0], c0[1])) & mpat(mlo);
            ap[1] = hex2(h2(c0[2], c0[3])) & mpat(mhi);
            ap[2] = hex2(h2(c1[0], c1[1])) & mpat(mlo >> 8);
            ap[3] = hex2(h2(c1[2], c1[3])) & mpat(mhi >> 8);
            mma16816(o[f][0], ap, vb0, vb1);
            mma16816(o[f][1], ap, vb2, vb3);
            mma16816(lsum[f], ap, ONES2, ONES2);
        }
        kb0=nk0; kb1=nk1; kb2=nk2; kb3=nk3;
        vb0=nv0; vb1=nv1; vb2=nv2; vb3=nv3;
    }

    // normalize and stage attn output tile (fp16) to smem
    #pragma unroll
    for (int f=0; f<2; ++f){
        float inv0 = rcpf(lsum[f][0]);
        float inv1 = rcpf(lsum[f][2]);
        #pragma unroll
        for (int t=0; t<2; ++t){
            *(unsigned*)&Xs[rbase + f*16 + qr][h*16 + t*8 + ms]     = h2(o[f][t][0]*inv0, o[f][t][1]*inv0);
            *(unsigned*)&Xs[rbase + f*16 + 8 + qr][h*16 + t*8 + ms] = h2(o[f][t][2]*inv1, o[f][t][3]*inv1);
        }
    }
    __syncthreads();

    // ---- fused output projection: out(64x128) = Xs @ Wos^T + bo ----
    // warp wid: rows 16*rg, col quarter cq (32 cols)
    int rg = wid >> 2, cq = wid & 3;
    unsigned a2[8][4];
    {
        const unsigned* p = (const unsigned*)Xs + (16*rg + qr)*68 + lc;
        #pragma unroll
        for (int kt = 0; kt < 8; ++kt){
            a2[kt][0] = p[kt*8];
            a2[kt][1] = p[kt*8 + 8*68];
            a2[kt][2] = p[kt*8 + 4];
            a2[kt][3] = p[kt*8 + 8*68 + 4];
        }
    }
    #pragma unroll
    for (int j = 0; j < 4; ++j){
        float c[4] = {0.f,0.f,0.f,0.f};
        const unsigned* bp = (const unsigned*)Wos + (32*cq + 8*j + qr)*68 + lc;
        #pragma unroll
        for (int kt = 0; kt < 8; ++kt)
            mma16816(c, a2[kt], bp[kt*8], bp[kt*8 + 4]);
        int col = 32*cq + 8*j + ms;
        float b0 = bs[col], b1 = bs[col + 1];
        int r = (b<<10) + q0 + 16*rg + qr;
        *(float2*)&out[(size_t)r*NF + col]     = make_float2(c[0]+b0, c[1]+b1);
        *(float2*)&out[(size_t)(r+8)*NF + col] = make_float2(c[2]+b0, c[3]+b1);
    }
}

// -------- launcher --------
extern "C" void kernel_launch(void* const* d_in, const int* in_sizes, int n_in,
                              void* d_out, int out_size){
    const float* X  = (const float*)d_in[0];
    const float* A  = (const float*)d_in[1];
    const float* Wq = (const float*)d_in[2];
    const float* bq = (const float*)d_in[3];
    const float* Wk = (const float*)d_in[4];
    const float* bk = (const float*)d_in[5];
    const float* Wv = (const float*)d_in[6];
    const float* bv = (const float*)d_in[7];
    const float* Wo = (const float*)d_in[8];
    const float* bo = (const float*)d_in[9];
    float* out = (float*)d_out;

    const int SMEM1 = 70144;
    const int SMEM2 = 61184;
    cudaFuncSetAttribute(pre_kernel,  cudaFuncAttributeMaxDynamicSharedMemorySize, SMEM1);
    cudaFuncSetAttribute(attn_kernel, cudaFuncAttributeMaxDynamicSharedMemorySize, SMEM2);

    pre_kernel<<<704, 512, SMEM1>>>(X, A, Wq, bq, Wk, bk, Wv, bv);
    attn_kernel<<<128, 512, SMEM2>>>(Wo, bo, out);
}

// round 7
// speedup vs baseline: 2.7700x; 1.2656x over previous
#include <cuda_runtime.h>
#include <cuda_fp16.h>

#define NB 8
#define NN 1024
#define NF 128
#define NH 8

// -------- scratch (device globals; allocation is forbidden) --------
__device__ __half    g_Q[NB*NN*NF];      // [b*N+q][128], pre-scaled by log2e/4
__device__ __half    g_K[NB*NN*NF];      // [b*N+q][128]
__device__ __half    g_V[NB*NN*NF];      // [b][t16=q/16][o(128)][qi(16)]  (16-key tiled)
__device__ unsigned  g_mask[NB*NN*32];   // [b*N+q][word]; bit j of word w = A[..][w*32+j]>0

#define QSCALE 0.3606737602222409f   // log2(e)/4
#define ONES2  0x3C003C00u           // half2(1,1)

// attn smem layout (bytes)
#define SM_WOS   0        // Wos[128][136] half   = 34816
#define SM_XS    34816    // Xs[64][136]  half    = 17408
#define SM_MASK  52224    // smask[64][33] u32    = 8448
#define SM_BS    60672    // bs[128] float        = 512
#define SM_KS    61184    // Ks[2][32][136] half  = 17408  (8704/buf)
#define SM_VS    78592    // Vs[2][128][40] half  = 20480  (10240/buf)
#define SM_TOT   99072

// -------- helpers --------
static __device__ __forceinline__ float rcpf(float x){ float r; asm("rcp.approx.ftz.f32 %0,%1;":"=f"(r):"f"(x)); return r; }
static __device__ __forceinline__ unsigned h2(float a,float b){
    __half2 h = __floats2half2_rn(a,b); return *reinterpret_cast<unsigned*>(&h); }
static __device__ __forceinline__ unsigned hex2(unsigned x){
    unsigned r; asm("ex2.approx.f16x2 %0,%1;":"=r"(r):"r"(x)); return r; }
// expand low 2 bits -> per-half 0xFFFF masks
static __device__ __forceinline__ unsigned mpat(unsigned bits){
    unsigned t = (bits & 3u) * 0x4080u;
    unsigned r; asm("prmt.b32 %0,%1,%2,%3;":"=r"(r):"r"(t),"r"(0u),"r"(0x9988u));
    return r;
}
static __device__ __forceinline__ void mma16816(float c[4], const unsigned a[4], unsigned b0, unsigned b1){
    asm volatile("mma.sync.aligned.m16n8k16.row.col.f32.f16.f16.f32 "
                 "{%0,%1,%2,%3},{%4,%5,%6,%7},{%8,%9},{%0,%1,%2,%3};"
                 : "+f"(c[0]),"+f"(c[1]),"+f"(c[2]),"+f"(c[3])
                 : "r"(a[0]),"r"(a[1]),"r"(a[2]),"r"(a[3]),"r"(b0),"r"(b1));
}
static __device__ __forceinline__ void ldm4(unsigned r[4], unsigned addr){
    asm volatile("ldmatrix.sync.aligned.m8n8.x4.shared.b16 {%0,%1,%2,%3}, [%4];"
        : "=r"(r[0]),"=r"(r[1]),"=r"(r[2]),"=r"(r[3]) : "r"(addr));
}
static __device__ __forceinline__ void cpa16(unsigned dst, const void* src){
    asm volatile("cp.async.cg.shared.global [%0], [%1], 16;" :: "r"(dst), "l"(src) : "memory");
}

// ============ kernel 1: fused mask compaction + Q/K/V projections ============
__global__ __launch_bounds__(512) void pre_kernel(const float* __restrict__ X,
        const float* __restrict__ A,
        const float* __restrict__ Wq, const float* __restrict__ bq,
        const float* __restrict__ Wk, const float* __restrict__ bk,
        const float* __restrict__ Wv, const float* __restrict__ bv){
    int bid = blockIdx.x;
    int tid = threadIdx.x;
    int w = tid >> 5, lane = tid & 31;

    if (bid >= 192){
        int row = (bid - 192) * 16 + w;               // 0..8191 (b*N+q)
        const float* a = A + (size_t)row * NN;
        unsigned myw = 0;
        #pragma unroll
        for (int j = 0; j < 32; ++j){
            unsigned m = __ballot_sync(0xffffffffu, a[j*32 + lane] > 0.0f);
            if (lane == j) myw = m;
        }
        g_mask[(size_t)row * 32 + lane] = myw;
        return;
    }

    extern __shared__ char smem[];
    __half (*Xs)[136] = (__half(*)[136])smem;
    __half (*Ws)[136] = (__half(*)[136])(smem + 34816);
    float*  bs        = (float*)(smem + 69632);

    int mode = bid >> 6;        // 0=Q 1=K 2=V
    int tile = bid & 63;
    const float* Wp = (mode == 0) ? Wq : (mode == 1) ? Wk : Wv;
    const float* bp = (mode == 0) ? bq : (mode == 1) ? bk : bv;
    int row0 = tile * 128;

    for (int i = tid; i < 4096; i += 512){
        int r = i >> 5, c4 = (i & 31) * 4;
        float4 v = *(const float4*)&X[(size_t)(row0 + r)*NF + c4];
        uint2 u; u.x = h2(v.x, v.y); u.y = h2(v.z, v.w);
        *(uint2*)&Xs[r][c4] = u;
        float4 ww = *(const float4*)&Wp[(size_t)r*NF + c4];
        uint2 uw; uw.x = h2(ww.x, ww.y); uw.y = h2(ww.z, ww.w);
        *(uint2*)&Ws[r][c4] = uw;
    }
    if (tid < 128) bs[tid] = bp[tid];
    __syncthreads();

    int qr = lane >> 2, lc = lane & 3, ms = lc * 2;
    int rg = w >> 1, ch = w & 1;

    const unsigned* Ab = (mode == 2) ? (const unsigned*)Ws : (const unsigned*)Xs;
    const unsigned* Bb = (mode == 2) ? (const unsigned*)Xs : (const unsigned*)Ws;

    unsigned a[8][4];
    {
        const unsigned* p = Ab + (16*rg + qr)*68 + lc;
        #pragma unroll
        for (int kt = 0; kt < 8; ++kt){
            a[kt][0] = p[kt*8];
            a[kt][1] = p[kt*8 + 8*68];
            a[kt][2] = p[kt*8 + 4];
            a[kt][3] = p[kt*8 + 8*68 + 4];
        }
    }

    float c[8][4];
    #pragma unroll
    for (int j = 0; j < 8; ++j){ c[j][0]=0.f; c[j][1]=0.f; c[j][2]=0.f; c[j][3]=0.f; }
    #pragma unroll
    for (int j = 0; j < 8; ++j){
        const unsigned* bpq = Bb + (64*ch + 8*j + qr)*68 + lc;
        #pragma unroll
        for (int kt = 0; kt < 8; ++kt)
            mma16816(c[j], a[kt], bpq[kt*8], bpq[kt*8 + 4]);
    }

    int b = row0 >> 10, q0 = row0 & (NN - 1);
    #pragma unroll
    for (int j = 0; j < 8; ++j){
        if (mode == 2){
            int o0 = 16*rg + qr, o1 = o0 + 8;
            int qg = q0 + 64*ch + 8*j + ms;        // global q within batch
            int t16 = qg >> 4, qi = qg & 15;
            float b0 = bs[o0], b1 = bs[o1];
            __half* base = g_V + ((size_t)(b*64 + t16) * 128) * 16;
            *(unsigned*)&base[o0*16 + qi] = h2(c[j][0]+b0, c[j][1]+b0);
            *(unsigned*)&base[o1*16 + qi] = h2(c[j][2]+b1, c[j][3]+b1);
        } else {
            int col = 64*ch + 8*j + ms;
            float b0 = bs[col], b1 = bs[col + 1];
            int r = row0 + 16*rg + qr;
            if (mode == 0){
                *(unsigned*)&g_Q[(size_t)r*NF + col]     = h2((c[j][0]+b0)*QSCALE, (c[j][1]+b1)*QSCALE);
                *(unsigned*)&g_Q[(size_t)(r+8)*NF + col] = h2((c[j][2]+b0)*QSCALE, (c[j][3]+b1)*QSCALE);
            } else {
                *(unsigned*)&g_K[(size_t)r*NF + col]     = h2(c[j][0]+b0, c[j][1]+b1);
                *(unsigned*)&g_K[(size_t)(r+8)*NF + col] = h2(c[j][2]+b0, c[j][3]+b1);
            }
        }
    }
}

// ============ kernel 2: masked flash attention + fused output projection ============
// grid 128 (b, q0-tile of 64), 512 threads: warp = (half, head)
// K/V staged to smem via cp.async (32 keys/iter, double buffered), ldmatrix fragments
__global__ __launch_bounds__(512) void attn_kernel(const float* __restrict__ Wo,
        const float* __restrict__ bo, float* __restrict__ out){
    extern __shared__ char smem[];
    __half   (*Wos)[136]  = (__half(*)[136])(smem + SM_WOS);
    __half   (*Xs)[136]   = (__half(*)[136])(smem + SM_XS);
    unsigned (*smask)[33] = (unsigned(*)[33])(smem + SM_MASK);
    float*    bs          = (float*)(smem + SM_BS);
    const unsigned smem_u = (unsigned)__cvta_generic_to_shared(smem);

    int tid = threadIdx.x;
    int b  = blockIdx.x >> 4;
    int q0 = (blockIdx.x & 15) * 64;
    int wid = tid >> 5, lane = tid & 31;
    int h = wid & 7, half = wid >> 3;

    // stage Wo (fp32->fp16), bias, mask
    for (int i = tid; i < 4096; i += 512){
        int r = i >> 5, c4 = (i & 31) * 4;
        float4 v = *(const float4*)&Wo[(size_t)r*NF + c4];
        uint2 u; u.x = h2(v.x, v.y); u.y = h2(v.z, v.w);
        *(uint2*)&Wos[r][c4] = u;
    }
    if (tid < 128) bs[tid] = bo[tid];
    for (int i = tid; i < 2048; i += 512){
        int r = i >> 5, ww = i & 31;
        smask[r][ww] = g_mask[(size_t)((b<<10) + q0 + r)*32 + ww];
    }

    int qr = lane >> 2;
    int lc = lane & 3;
    int ms = lc * 2;
    int rbase = 32*half;

    unsigned a[2][4];
    #pragma unroll
    for (int f=0; f<2; ++f){
        const __half* Qp = g_Q + (((size_t)((b<<10) + q0 + rbase + f*16 + qr)) << 7) + h*16;
        a[f][0] = *(const unsigned*)(Qp + ms);
        a[f][2] = *(const unsigned*)(Qp + ms + 8);
        const __half* Qp8 = Qp + (8 << 7);
        a[f][1] = *(const unsigned*)(Qp8 + ms);
        a[f][3] = *(const unsigned*)(Qp8 + ms + 8);
    }

    float o[2][2][4];
    float lsum[2][4];
    #pragma unroll
    for (int f=0;f<2;++f){
        #pragma unroll
        for (int j=0;j<4;++j) lsum[f][j]=0.f;
        #pragma unroll
        for (int t=0;t<2;++t){ o[f][t][0]=0.f;o[f][t][1]=0.f;o[f][t][2]=0.f;o[f][t][3]=0.f; }
    }

    // per-thread staging descriptors
    const int krow = tid >> 4, kch = tid & 15;               // K: 32 rows x 16 chunks
    const int vo = tid >> 2, vc = tid & 3;                   // V: 128 rows x 4 chunks
    const unsigned kdst = smem_u + SM_KS + (krow*136 + kch*8)*2;
    const unsigned vdst = smem_u + SM_VS + (vo*40 + vc*8)*2;
    const __half* ksrc0 = g_K + ((size_t)(b<<10) + krow)*NF + kch*8;
    const __half* vsrc0 = g_V + ((size_t)(b*64 + (vc>>1))*128 + vo)*16 + (vc&1)*8;

    #define STAGE(it, buf) do { \
        cpa16(kdst + (buf)*8704,  ksrc0 + (size_t)(it)*32*NF); \
        cpa16(vdst + (buf)*10240, vsrc0 + (size_t)(it)*2*2048); \
        asm volatile("cp.async.commit_group;" ::: "memory"); \
    } while(0)

    STAGE(0, 0);
    STAGE(1, 1);

    // per-thread ldmatrix address offsets (within a buffer)
    const unsigned kfrag = smem_u + SM_KS +
        ((((lane>>4)&1)*8 + (lane&7))*136 + h*16 + ((lane>>3)&1)*8)*2;
    const unsigned vfrag = smem_u + SM_VS +
        ((h*16 + ((lane>>4)&1)*8 + (lane&7))*40 + ((lane>>3)&1)*8)*2;

    for (int it = 0; it < 32; ++it){
        int buf = it & 1;
        if (it < 31) asm volatile("cp.async.wait_group 1;" ::: "memory");
        else         asm volatile("cp.async.wait_group 0;" ::: "memory");
        __syncthreads();

        #pragma unroll
        for (int sub = 0; sub < 2; ++sub){
            unsigned kb[4], vb[4];
            ldm4(kb, kfrag + buf*8704 + sub*16*136*2);
            ldm4(vb, vfrag + buf*10240 + sub*32);
            int sbms = (sub << 4) + ms;
            #pragma unroll
            for (int f=0; f<2; ++f){
                float c0[4] = {0.f,0.f,0.f,0.f};
                float c1[4] = {0.f,0.f,0.f,0.f};
                mma16816(c0, a[f], kb[0], kb[1]);
                mma16816(c1, a[f], kb[2], kb[3]);
                unsigned mlo = smask[rbase + f*16 + qr][it]     >> sbms;
                unsigned mhi = smask[rbase + f*16 + 8 + qr][it] >> sbms;
                unsigned ap[4];
                ap[0] = hex2(h2(c0[0], c0[1])) & mpat(mlo);
                ap[1] = hex2(h2(c0[2], c0[3])) & mpat(mhi);
                ap[2] = hex2(h2(c1[0], c1[1])) & mpat(mlo >> 8);
                ap[3] = hex2(h2(c1[2], c1[3])) & mpat(mhi >> 8);
                mma16816(o[f][0], ap, vb[0], vb[1]);
                mma16816(o[f][1], ap, vb[2], vb[3]);
                mma16816(lsum[f], ap, ONES2, ONES2);
            }
        }
        __syncthreads();
        if (it + 2 <= 31) STAGE(it + 2, buf);
    }

    // normalize and stage attn output tile (fp16) to smem
    #pragma unroll
    for (int f=0; f<2; ++f){
        float inv0 = rcpf(lsum[f][0]);
        float inv1 = rcpf(lsum[f][2]);
        #pragma unroll
        for (int t=0; t<2; ++t){
            *(unsigned*)&Xs[rbase + f*16 + qr][h*16 + t*8 + ms]     = h2(o[f][t][0]*inv0, o[f][t][1]*inv0);
            *(unsigned*)&Xs[rbase + f*16 + 8 + qr][h*16 + t*8 + ms] = h2(o[f][t][2]*inv1, o[f][t][3]*inv1);
        }
    }
    __syncthreads();

    // ---- fused output projection: out(64x128) = Xs @ Wos^T + bo ----
    int rg = wid >> 2, cq = wid & 3;
    unsigned a2[8][4];
    {
        const unsigned* p = (const unsigned*)Xs + (16*rg + qr)*68 + lc;
        #pragma unroll
        for (int kt = 0; kt < 8; ++kt){
            a2[kt][0] = p[kt*8];
            a2[kt][1] = p[kt*8 + 8*68];
            a2[kt][2] = p[kt*8 + 4];
            a2[kt][3] = p[kt*8 + 8*68 + 4];
        }
    }
    #pragma unroll
    for (int j = 0; j < 4; ++j){
        float c[4] = {0.f,0.f,0.f,0.f};
        const unsigned* bp = (const unsigned*)Wos + (32*cq + 8*j + qr)*68 + lc;
        #pragma unroll
        for (int kt = 0; kt < 8; ++kt)
            mma16816(c, a2[kt], bp[kt*8], bp[kt*8 + 4]);
        int col = 32*cq + 8*j + ms;
        float b0 = bs[col], b1 = bs[col + 1];
        int r = (b<<10) + q0 + 16*rg + qr;
        *(float2*)&out[(size_t)r*NF + col]     = make_float2(c[0]+b0, c[1]+b1);
        *(float2*)&out[(size_t)(r+8)*NF + col] = make_float2(c[2]+b0, c[3]+b1);
    }
}

// -------- launcher --------
extern "C" void kernel_launch(void* const* d_in, const int* in_sizes, int n_in,
                              void* d_out, int out_size){
    const float* X  = (const float*)d_in[0];
    const float* A  = (const float*)d_in[1];
    const float* Wq = (const float*)d_in[2];
    const float* bq = (const float*)d_in[3];
    const float* Wk = (const float*)d_in[4];
    const float* bk = (const float*)d_in[5];
    const float* Wv = (const float*)d_in[6];
    const float* bv = (const float*)d_in[7];
    const float* Wo = (const float*)d_in[8];
    const float* bo = (const float*)d_in[9];
    float* out = (float*)d_out;

    const int SMEM1 = 70144;
    cudaFuncSetAttribute(pre_kernel,  cudaFuncAttributeMaxDynamicSharedMemorySize, SMEM1);
    cudaFuncSetAttribute(attn_kernel, cudaFuncAttributeMaxDynamicSharedMemorySize, SM_TOT);

    pre_kernel<<<704, 512, SMEM1>>>(X, A, Wq, bq, Wk, bk, Wv, bv);
    attn_kernel<<<128, 512, SM_TOT>>>(Wo, bo, out);
}